// round 1
// baseline (speedup 1.0000x reference)
#include <cuda_runtime.h>
#include <math.h>

#define THREADS 256
#define TILE    128
#define EDIM    64
#define HDIM    128
#define KBINS   32
#define PDIM    95
#define LNUM    6
#define NBNUM   2
#define TBV     6.0f
#define MINBIN  0.001f
#define MINDER  0.001f

typedef unsigned long long ull;

__device__ __forceinline__ ull dup2(float x) {
    ull r; asm("mov.b64 %0, {%1,%1};" : "=l"(r) : "f"(x)); return r;
}
__device__ __forceinline__ void unpack2(ull v, float& a, float& b) {
    asm("mov.b64 {%0,%1}, %2;" : "=f"(a), "=f"(b) : "l"(v));
}
__device__ __forceinline__ void fma2(ull& d, ull a, ull b) {
    asm("fma.rn.f32x2 %0, %1, %2, %0;" : "+l"(d) : "l"(a), "l"(b));
}

__device__ __forceinline__ float eluf(float x)  { return x > 0.f ? x : expm1f(x); }
__device__ __forceinline__ float sigmf(float x) { return 1.0f / (1.0f + expf(-x)); }
__device__ __forceinline__ float softplusf(float x) {
    return fmaxf(x, 0.f) + log1pf(expf(-fabsf(x)));
}

template<int NH>
__device__ __forceinline__ void zacc(ull (&a)[NH][4]) {
    #pragma unroll
    for (int i = 0; i < NH; ++i)
        #pragma unroll
        for (int j = 0; j < 4; ++j) a[i][j] = 0ull;
}

// out^T[c][i] = sum_k W[k][c] * X^T[k][i]; thread owns samples si..si+3, cols c0..c0+NPT-1
// NSTR: weight row stride (== N); KC: K rows per smem chunk (KC*NSTR == 4096)
template<int NPT, int NSTR, int KC>
__device__ __forceinline__ void gemm_dense(
    ull (&accp)[NPT/2][4],
    const float* __restrict__ Xs,
    const float* __restrict__ Wg,
    float* __restrict__ wbuf,
    int KDIM, int tx, int si, int c0)
{
    for (int k0 = 0; k0 < KDIM; k0 += KC) {
        const float4* src = (const float4*)(Wg + (size_t)k0 * NSTR);
        float4* dst = (float4*)wbuf;
        #pragma unroll
        for (int it = 0; it < (KC * NSTR) / (4 * THREADS); ++it)
            dst[it * THREADS + tx] = src[it * THREADS + tx];
        __syncthreads();
        const float* Xc = Xs + k0 * TILE + si;
        #pragma unroll 4
        for (int k = 0; k < KC; ++k) {
            float4 xv = *(const float4*)(Xc + k * TILE);
            ull x0 = dup2(xv.x), x1 = dup2(xv.y), x2 = dup2(xv.z), x3 = dup2(xv.w);
            const ull* wr = (const ull*)(wbuf + k * NSTR + c0);
            #pragma unroll
            for (int cp = 0; cp < NPT / 2; ++cp) {
                ull w2 = wr[cp];
                fma2(accp[cp][0], w2, x0);
                fma2(accp[cp][1], w2, x1);
                fma2(accp[cp][2], w2, x2);
                fma2(accp[cp][3], w2, x3);
            }
        }
        __syncthreads();
    }
}

template<int NPT, class F>
__device__ __forceinline__ void epi(ull (&accp)[NPT/2][4], int c0, F f) {
    #pragma unroll
    for (int cp = 0; cp < NPT / 2; ++cp) {
        float4 vl, vh;
        unpack2(accp[cp][0], vl.x, vh.x);
        unpack2(accp[cp][1], vl.y, vh.y);
        unpack2(accp[cp][2], vl.z, vh.z);
        unpack2(accp[cp][3], vl.w, vh.w);
        f(c0 + 2 * cp,     vl);
        f(c0 + 2 * cp + 1, vh);
    }
}

__global__ void __launch_bounds__(THREADS, 1)
nsf_kernel(const float* __restrict__ y,      const float* __restrict__ context,
           const float* __restrict__ eW1,    const float* __restrict__ eb1,
           const float* __restrict__ eW2,    const float* __restrict__ eb2,
           const float* __restrict__ eW3,    const float* __restrict__ eb3,
           const float* __restrict__ init_b, const float* __restrict__ ctx_W,
           const float* __restrict__ ctx_b,  const float* __restrict__ blk_W1,
           const float* __restrict__ blk_b1, const float* __restrict__ blk_W2,
           const float* __restrict__ blk_b2, const float* __restrict__ blk_Wc,
           const float* __restrict__ blk_bc, const float* __restrict__ out_W,
           const float* __restrict__ out_b,  float* __restrict__ outp)
{
    extern __shared__ float smem[];
    float* hT   = smem;                               // [128][128] (also spline scratch)
    float* tbuf = smem + HDIM * TILE;                 // [128][128]
    float* embT = smem + 2 * HDIM * TILE;             // [64][128]
    float* wbuf = smem + 2 * HDIM * TILE + EDIM * TILE; // 4096 floats

    const int tx   = threadIdx.x;
    const int base = blockIdx.x * TILE;
    const int si   = (tx & 31) * 4;   // sample offset within tile
    const int cg   = tx >> 5;         // column group 0..7

    // persistent spline state (threads 0..127)
    float zv = 0.f, ladv = 0.f;
    if (tx < TILE) zv = y[base + tx];

    // ---------------- embedding ----------------
    {
        int ii = tx & 127, cd = tx >> 7;
        wbuf[cd * TILE + ii] = context[(size_t)(base + ii) * 2 + cd];
    }
    __syncthreads();
    for (int idx = tx; idx < EDIM * TILE; idx += THREADS) {
        int c = idx >> 7, ii = idx & 127;
        float v = eb1[c] + wbuf[ii] * eW1[c] + wbuf[TILE + ii] * eW1[EDIM + c];
        embT[idx] = eluf(v);
    }
    __syncthreads();
    {
        const int c0e = cg * 8;
        ull acce[4][4];
        zacc<4>(acce);
        gemm_dense<8, 64, 64>(acce, embT, eW2, wbuf, EDIM, tx, si, c0e);
        epi<8>(acce, c0e, [&](int c, float4 v) {
            float b = eb2[c];
            float4 o = {eluf(v.x + b), eluf(v.y + b), eluf(v.z + b), eluf(v.w + b)};
            *(float4*)(tbuf + c * TILE + si) = o;
        });
        __syncthreads();
        zacc<4>(acce);
        gemm_dense<8, 64, 64>(acce, tbuf, eW3, wbuf, EDIM, tx, si, c0e);
        epi<8>(acce, c0e, [&](int c, float4 v) {
            float b = eb3[c];
            float4 o = {eluf(v.x + b), eluf(v.y + b), eluf(v.z + b), eluf(v.w + b)};
            *(float4*)(embT + c * TILE + si) = o;
        });
        __syncthreads();
    }

    // ---------------- flow layers ----------------
    ull acc[8][4];
    const int c0 = cg * 16;
    for (int l = 0; l < LNUM; ++l) {
        // h = init_b + emb @ ctx_W + ctx_b
        zacc<8>(acc);
        gemm_dense<16, 128, 32>(acc, embT, ctx_W + (size_t)l * EDIM * HDIM, wbuf, EDIM, tx, si, c0);
        {
            const float* bA = init_b + l * HDIM;
            const float* bB = ctx_b  + l * HDIM;
            epi<16>(acc, c0, [&](int c, float4 v) {
                float b = bA[c] + bB[c];
                float4 o = {v.x + b, v.y + b, v.z + b, v.w + b};
                *(float4*)(hT + c * TILE + si) = o;
            });
        }
        __syncthreads();

        for (int j = 0; j < NBNUM; ++j) {
            const int lj = l * NBNUM + j;
            // elu(h) -> tbuf
            for (int idx = tx; idx < (HDIM * TILE) / 4; idx += THREADS) {
                float4 v = ((const float4*)hT)[idx];
                v.x = eluf(v.x); v.y = eluf(v.y); v.z = eluf(v.z); v.w = eluf(v.w);
                ((float4*)tbuf)[idx] = v;
            }
            __syncthreads();
            // t1 = elu(elu(h) @ W1 + b1) -> tbuf
            zacc<8>(acc);
            gemm_dense<16, 128, 32>(acc, tbuf, blk_W1 + (size_t)lj * HDIM * HDIM, wbuf, HDIM, tx, si, c0);
            {
                const float* bp = blk_b1 + lj * HDIM;
                epi<16>(acc, c0, [&](int c, float4 v) {
                    float b = bp[c];
                    float4 o = {eluf(v.x + b), eluf(v.y + b), eluf(v.z + b), eluf(v.w + b)};
                    *(float4*)(tbuf + c * TILE + si) = o;
                });
            }
            __syncthreads();
            // t2 = t1 @ W2 + b2 -> tbuf
            zacc<8>(acc);
            gemm_dense<16, 128, 32>(acc, tbuf, blk_W2 + (size_t)lj * HDIM * HDIM, wbuf, HDIM, tx, si, c0);
            {
                const float* bp = blk_b2 + lj * HDIM;
                epi<16>(acc, c0, [&](int c, float4 v) {
                    float b = bp[c];
                    float4 o = {v.x + b, v.y + b, v.z + b, v.w + b};
                    *(float4*)(tbuf + c * TILE + si) = o;
                });
            }
            __syncthreads();
            // h += t2 * sigmoid(emb @ Wc + bc)
            zacc<8>(acc);
            gemm_dense<16, 128, 32>(acc, embT, blk_Wc + (size_t)lj * EDIM * HDIM, wbuf, EDIM, tx, si, c0);
            {
                const float* bp = blk_bc + lj * HDIM;
                epi<16>(acc, c0, [&](int c, float4 v) {
                    float b = bp[c];
                    float4 t  = *(const float4*)(tbuf + c * TILE + si);
                    float4 h4 = *(const float4*)(hT   + c * TILE + si);
                    h4.x += t.x * sigmf(v.x + b);
                    h4.y += t.y * sigmf(v.y + b);
                    h4.z += t.z * sigmf(v.z + b);
                    h4.w += t.w * sigmf(v.w + b);
                    *(float4*)(hT + c * TILE + si) = h4;
                });
            }
            __syncthreads();
        }

        // p^T = (h @ out_W[l] + out_b[l])^T -> tbuf  (N=95, staged stride 96)
        {
            ull acco[6][4];
            zacc<6>(acco);
            const int c0o = cg * 12;
            const float* Wg = out_W + (size_t)l * HDIM * PDIM;
            for (int k0 = 0; k0 < HDIM; k0 += 32) {
                for (int idx = tx; idx < 32 * PDIM; idx += THREADS) {
                    int k = idx / PDIM;
                    int c = idx - k * PDIM;
                    wbuf[k * 96 + c] = Wg[(size_t)(k0 + k) * PDIM + c];
                }
                __syncthreads();
                #pragma unroll 4
                for (int k = 0; k < 32; ++k) {
                    float4 xv = *(const float4*)(hT + (k0 + k) * TILE + si);
                    ull x0 = dup2(xv.x), x1 = dup2(xv.y), x2 = dup2(xv.z), x3 = dup2(xv.w);
                    const ull* wr = (const ull*)(wbuf + k * 96 + c0o);
                    #pragma unroll
                    for (int cp = 0; cp < 6; ++cp) {
                        ull w2 = wr[cp];
                        fma2(acco[cp][0], w2, x0);
                        fma2(acco[cp][1], w2, x1);
                        fma2(acco[cp][2], w2, x2);
                        fma2(acco[cp][3], w2, x3);
                    }
                }
                __syncthreads();
            }
            const float* bp = out_b + l * PDIM;
            epi<12>(acco, c0o, [&](int c, float4 v) {
                if (c < PDIM) {
                    float b = bp[c];
                    float4 o = {v.x + b, v.y + b, v.z + b, v.w + b};
                    *(float4*)(tbuf + c * TILE + si) = o;
                }
            });
        }
        __syncthreads();

        // ---------------- rational-quadratic spline (1 thread / sample) ----------------
        if (tx < TILE) {
            const float invscale = 0.08838834764831845f;          // 1/sqrt(128)
            const float alpha    = 1.0f - MINBIN * (float)KBINS;  // 0.968
            float* scr = hT;       // free scratch: cw rows 0..32, ch 33..65, d 66..98
            const float* p = tbuf; // p^T
            const float yv  = zv;
            const float ycv = fminf(fmaxf(yv, -TBV), TBV);
            const bool inside = (yv >= -TBV) && (yv <= TBV);

            #pragma unroll
            for (int t = 0; t < 2; ++t) {   // t=0: widths->cw, t=1: heights->ch
                const int po = t * KBINS;
                const int so = t * 33;
                float m = -1e30f;
                for (int k = 0; k < KBINS; ++k)
                    m = fmaxf(m, p[(po + k) * TILE + tx] * invscale);
                float S = 0.f;
                for (int k = 0; k < KBINS; ++k) {
                    float e = expf(p[(po + k) * TILE + tx] * invscale - m);
                    S += e;
                    scr[(so + k + 1) * TILE + tx] = e;
                }
                float inv = 1.0f / S;
                float cs = 0.f;
                scr[so * TILE + tx] = -TBV;
                for (int k = 1; k < KBINS; ++k) {
                    cs += scr[(so + k) * TILE + tx];
                    scr[(so + k) * TILE + tx] =
                        2.0f * TBV * (MINBIN * (float)k + alpha * cs * inv) - TBV;
                }
                scr[(so + KBINS) * TILE + tx] = TBV;
            }
            {
                const float dedge = MINDER + softplusf(logf(expf(1.0f - MINDER) - 1.0f));
                scr[66 * TILE + tx] = dedge;
                for (int k = 1; k < KBINS; ++k)
                    scr[(66 + k) * TILE + tx] =
                        MINDER + softplusf(p[(2 * KBINS + k - 1) * TILE + tx]);
                scr[(66 + KBINS) * TILE + tx] = dedge;
            }
            int cnt = 0;
            for (int k = 0; k <= KBINS; ++k) {
                float loc = scr[k * TILE + tx];
                if (k == KBINS) loc += 1e-6f;
                cnt += (ycv >= loc) ? 1 : 0;
            }
            int idx = min(cnt - 1, KBINS - 1);
            if (idx < 0) idx = 0;
            float cwk = scr[idx * TILE + tx];
            float wk  = scr[(idx + 1) * TILE + tx] - cwk;
            float chk = scr[(33 + idx) * TILE + tx];
            float hk  = scr[(34 + idx) * TILE + tx] - chk;
            float dk  = scr[(66 + idx) * TILE + tx];
            float dk1 = scr[(67 + idx) * TILE + tx];
            float sk   = hk / wk;
            float th   = (ycv - cwk) / wk;
            float om   = 1.0f - th;
            float th1m = th * om;
            float num  = hk * (sk * th * th + dk * th1m);
            float den  = sk + (dk + dk1 - 2.0f * sk) * th1m;
            float outv = chk + num / den;
            float dnum = sk * sk * (dk1 * th * th + 2.0f * sk * th1m + dk * om * om);
            float ladl = logf(dnum) - 2.0f * logf(den);
            if (inside) { zv = outv; ladv += ladl; }
        }
        __syncthreads();
    }

    if (tx < TILE)
        outp[base + tx] = -0.5f * zv * zv - 0.91893853320467274178f + ladv;
}

extern "C" void kernel_launch(void* const* d_in, const int* in_sizes, int n_in,
                              void* d_out, int out_size)
{
    const float* y       = (const float*)d_in[0];
    const float* context = (const float*)d_in[1];
    const float* eW1     = (const float*)d_in[2];
    const float* eb1     = (const float*)d_in[3];
    const float* eW2     = (const float*)d_in[4];
    const float* eb2     = (const float*)d_in[5];
    const float* eW3     = (const float*)d_in[6];
    const float* eb3     = (const float*)d_in[7];
    const float* init_b  = (const float*)d_in[8];
    const float* ctx_W   = (const float*)d_in[9];
    const float* ctx_b   = (const float*)d_in[10];
    const float* blk_W1  = (const float*)d_in[11];
    const float* blk_b1  = (const float*)d_in[12];
    const float* blk_W2  = (const float*)d_in[13];
    const float* blk_b2  = (const float*)d_in[14];
    const float* blk_Wc  = (const float*)d_in[15];
    const float* blk_bc  = (const float*)d_in[16];
    const float* out_W   = (const float*)d_in[17];
    const float* out_b   = (const float*)d_in[18];

    const int B = in_sizes[0];          // 262144
    const int grid = B / TILE;          // 2048
    const size_t smem = (size_t)(2 * HDIM * TILE + EDIM * TILE + 4096) * sizeof(float); // 180224 B

    cudaFuncSetAttribute(nsf_kernel, cudaFuncAttributeMaxDynamicSharedMemorySize, (int)smem);
    nsf_kernel<<<grid, THREADS, smem>>>(
        y, context, eW1, eb1, eW2, eb2, eW3, eb3, init_b, ctx_W, ctx_b,
        blk_W1, blk_b1, blk_W2, blk_b2, blk_Wc, blk_bc, out_W, out_b,
        (float*)d_out);
}

// round 5
// speedup vs baseline: 1.2206x; 1.2206x over previous
#include <cuda_runtime.h>
#include <math.h>

#define THREADS 256
#define TILE    64
#define EDIM    64
#define HDIM    128
#define KBINS   32
#define PDIM    95
#define LNUM    6
#define NBNUM   2
#define TBV     6.0f
#define MINBIN  0.001f
#define MINDER  0.001f

typedef unsigned long long ull;

__device__ __forceinline__ ull dup2(float x) {
    ull r; asm("mov.b64 %0, {%1,%1};" : "=l"(r) : "f"(x)); return r;
}
__device__ __forceinline__ void unpack2(ull v, float& a, float& b) {
    asm("mov.b64 {%0,%1}, %2;" : "=f"(a), "=f"(b) : "l"(v));
}
__device__ __forceinline__ void fma2(ull& d, ull a, ull b) {
    asm("fma.rn.f32x2 %0, %1, %2, %0;" : "+l"(d) : "l"(a), "l"(b));
}

__device__ __forceinline__ float eluf(float x)  { return x > 0.f ? x : expm1f(x); }
__device__ __forceinline__ float sigmf(float x) { return 1.0f / (1.0f + expf(-x)); }
__device__ __forceinline__ float softplusf(float x) {
    return fmaxf(x, 0.f) + log1pf(expf(-fabsf(x)));
}

template<int NH>
__device__ __forceinline__ void zacc(ull (&a)[NH][4]) {
    #pragma unroll
    for (int i = 0; i < NH; ++i)
        #pragma unroll
        for (int j = 0; j < 4; ++j) a[i][j] = 0ull;
}

// out^T[c][i] = sum_k W[k][c] * X^T[k][i]; thread owns samples si..si+3, cols c0..c0+NPT-1
// NSTR: weight row stride (== N); KC: K rows per smem chunk (KC*NSTR == 4096)
template<int NPT, int NSTR, int KC>
__device__ __forceinline__ void gemm_dense(
    ull (&accp)[NPT/2][4],
    const float* __restrict__ Xs,
    const float* __restrict__ Wg,
    float* __restrict__ wbuf,
    int KDIM, int tx, int si, int c0)
{
    for (int k0 = 0; k0 < KDIM; k0 += KC) {
        const float4* src = (const float4*)(Wg + (size_t)k0 * NSTR);
        float4* dst = (float4*)wbuf;
        #pragma unroll
        for (int it = 0; it < (KC * NSTR) / (4 * THREADS); ++it)
            dst[it * THREADS + tx] = src[it * THREADS + tx];
        __syncthreads();
        const float* Xc = Xs + k0 * TILE + si;
        #pragma unroll 8
        for (int k = 0; k < KC; ++k) {
            float4 xv = *(const float4*)(Xc + k * TILE);
            ull x0 = dup2(xv.x), x1 = dup2(xv.y), x2 = dup2(xv.z), x3 = dup2(xv.w);
            const ull* wr = (const ull*)(wbuf + k * NSTR + c0);
            #pragma unroll
            for (int cp = 0; cp < NPT / 2; ++cp) {
                ull w2 = wr[cp];
                fma2(accp[cp][0], w2, x0);
                fma2(accp[cp][1], w2, x1);
                fma2(accp[cp][2], w2, x2);
                fma2(accp[cp][3], w2, x3);
            }
        }
        __syncthreads();
    }
}

template<int NPT, class F>
__device__ __forceinline__ void epi(ull (&accp)[NPT/2][4], int c0, F f) {
    #pragma unroll
    for (int cp = 0; cp < NPT / 2; ++cp) {
        float4 vl, vh;
        unpack2(accp[cp][0], vl.x, vh.x);
        unpack2(accp[cp][1], vl.y, vh.y);
        unpack2(accp[cp][2], vl.z, vh.z);
        unpack2(accp[cp][3], vl.w, vh.w);
        f(c0 + 2 * cp,     vl);
        f(c0 + 2 * cp + 1, vh);
    }
}

__global__ void __launch_bounds__(THREADS, 2)
nsf_kernel(const float* __restrict__ y,      const float* __restrict__ context,
           const float* __restrict__ eW1,    const float* __restrict__ eb1,
           const float* __restrict__ eW2,    const float* __restrict__ eb2,
           const float* __restrict__ eW3,    const float* __restrict__ eb3,
           const float* __restrict__ init_b, const float* __restrict__ ctx_W,
           const float* __restrict__ ctx_b,  const float* __restrict__ blk_W1,
           const float* __restrict__ blk_b1, const float* __restrict__ blk_W2,
           const float* __restrict__ blk_b2, const float* __restrict__ blk_Wc,
           const float* __restrict__ blk_bc, const float* __restrict__ out_W,
           const float* __restrict__ out_b,  float* __restrict__ outp)
{
    extern __shared__ float smem[];
    float* hT   = smem;                                 // [128][64] (also spline scratch)
    float* tbuf = smem + HDIM * TILE;                   // [128][64]
    float* embT = smem + 2 * HDIM * TILE;               // [64][64]
    float* wbuf = smem + 2 * HDIM * TILE + EDIM * TILE; // 4096 floats

    const int tx   = threadIdx.x;
    const int base = blockIdx.x * TILE;
    const int si   = (tx & 15) * 4;   // sample offset within tile
    const int cg   = tx >> 4;         // column group 0..15

    // persistent spline state (threads 0..63)
    float zv = 0.f, ladv = 0.f;
    if (tx < TILE) zv = y[base + tx];

    // ---------------- embedding ----------------
    if (tx < 2 * TILE) {
        int ii = tx & 63, cd = tx >> 6;
        wbuf[cd * TILE + ii] = context[(size_t)(base + ii) * 2 + cd];
    }
    __syncthreads();
    for (int idx = tx; idx < EDIM * TILE; idx += THREADS) {
        int c = idx >> 6, ii = idx & 63;
        float v = eb1[c] + wbuf[ii] * eW1[c] + wbuf[TILE + ii] * eW1[EDIM + c];
        embT[idx] = eluf(v);
    }
    __syncthreads();
    {
        const int c0e = cg * 4;
        ull acce[2][4];
        zacc<2>(acce);
        gemm_dense<4, 64, 64>(acce, embT, eW2, wbuf, EDIM, tx, si, c0e);
        epi<4>(acce, c0e, [&](int c, float4 v) {
            float b = eb2[c];
            float4 o = {eluf(v.x + b), eluf(v.y + b), eluf(v.z + b), eluf(v.w + b)};
            *(float4*)(tbuf + c * TILE + si) = o;
        });
        __syncthreads();
        zacc<2>(acce);
        gemm_dense<4, 64, 64>(acce, tbuf, eW3, wbuf, EDIM, tx, si, c0e);
        epi<4>(acce, c0e, [&](int c, float4 v) {
            float b = eb3[c];
            float4 o = {eluf(v.x + b), eluf(v.y + b), eluf(v.z + b), eluf(v.w + b)};
            *(float4*)(embT + c * TILE + si) = o;
        });
        __syncthreads();
    }

    // ---------------- flow layers ----------------
    ull acc[4][4];
    const int c0 = cg * 8;
    for (int l = 0; l < LNUM; ++l) {
        // h = init_b + emb @ ctx_W + ctx_b
        zacc<4>(acc);
        gemm_dense<8, 128, 32>(acc, embT, ctx_W + (size_t)l * EDIM * HDIM, wbuf, EDIM, tx, si, c0);
        {
            const float* bA = init_b + l * HDIM;
            const float* bB = ctx_b  + l * HDIM;
            epi<8>(acc, c0, [&](int c, float4 v) {
                float b = bA[c] + bB[c];
                float4 o = {v.x + b, v.y + b, v.z + b, v.w + b};
                *(float4*)(hT + c * TILE + si) = o;
            });
        }
        __syncthreads();

        for (int j = 0; j < NBNUM; ++j) {
            const int lj = l * NBNUM + j;
            // elu(h) -> tbuf
            for (int idx = tx; idx < (HDIM * TILE) / 4; idx += THREADS) {
                float4 v = ((const float4*)hT)[idx];
                v.x = eluf(v.x); v.y = eluf(v.y); v.z = eluf(v.z); v.w = eluf(v.w);
                ((float4*)tbuf)[idx] = v;
            }
            __syncthreads();
            // t1 = elu(elu(h) @ W1 + b1) -> tbuf
            zacc<4>(acc);
            gemm_dense<8, 128, 32>(acc, tbuf, blk_W1 + (size_t)lj * HDIM * HDIM, wbuf, HDIM, tx, si, c0);
            {
                const float* bp = blk_b1 + lj * HDIM;
                epi<8>(acc, c0, [&](int c, float4 v) {
                    float b = bp[c];
                    float4 o = {eluf(v.x + b), eluf(v.y + b), eluf(v.z + b), eluf(v.w + b)};
                    *(float4*)(tbuf + c * TILE + si) = o;
                });
            }
            __syncthreads();
            // t2 = t1 @ W2 + b2 -> tbuf
            zacc<4>(acc);
            gemm_dense<8, 128, 32>(acc, tbuf, blk_W2 + (size_t)lj * HDIM * HDIM, wbuf, HDIM, tx, si, c0);
            {
                const float* bp = blk_b2 + lj * HDIM;
                epi<8>(acc, c0, [&](int c, float4 v) {
                    float b = bp[c];
                    float4 o = {v.x + b, v.y + b, v.z + b, v.w + b};
                    *(float4*)(tbuf + c * TILE + si) = o;
                });
            }
            __syncthreads();
            // h += t2 * sigmoid(emb @ Wc + bc)
            zacc<4>(acc);
            gemm_dense<8, 128, 32>(acc, embT, blk_Wc + (size_t)lj * EDIM * HDIM, wbuf, EDIM, tx, si, c0);
            {
                const float* bp = blk_bc + lj * HDIM;
                epi<8>(acc, c0, [&](int c, float4 v) {
                    float b = bp[c];
                    float4 t  = *(const float4*)(tbuf + c * TILE + si);
                    float4 h4 = *(const float4*)(hT   + c * TILE + si);
                    h4.x += t.x * sigmf(v.x + b);
                    h4.y += t.y * sigmf(v.y + b);
                    h4.z += t.z * sigmf(v.z + b);
                    h4.w += t.w * sigmf(v.w + b);
                    *(float4*)(hT + c * TILE + si) = h4;
                });
            }
            __syncthreads();
        }

        // p^T = (h @ out_W[l] + out_b[l])^T -> tbuf  (N=95, staged stride 96)
        {
            ull acco[3][4];
            zacc<3>(acco);
            const int c0o = cg * 6;
            const float* Wg = out_W + (size_t)l * HDIM * PDIM;
            for (int k0 = 0; k0 < HDIM; k0 += 32) {
                for (int idx = tx; idx < 32 * PDIM; idx += THREADS) {
                    int k = idx / PDIM;
                    int c = idx - k * PDIM;
                    wbuf[k * 96 + c] = Wg[(size_t)(k0 + k) * PDIM + c];
                }
                __syncthreads();
                #pragma unroll 8
                for (int k = 0; k < 32; ++k) {
                    float4 xv = *(const float4*)(hT + (k0 + k) * TILE + si);
                    ull x0 = dup2(xv.x), x1 = dup2(xv.y), x2 = dup2(xv.z), x3 = dup2(xv.w);
                    const ull* wr = (const ull*)(wbuf + k * 96 + c0o);
                    #pragma unroll
                    for (int cp = 0; cp < 3; ++cp) {
                        ull w2 = wr[cp];
                        fma2(acco[cp][0], w2, x0);
                        fma2(acco[cp][1], w2, x1);
                        fma2(acco[cp][2], w2, x2);
                        fma2(acco[cp][3], w2, x3);
                    }
                }
                __syncthreads();
            }
            const float* bp = out_b + l * PDIM;
            epi<6>(acco, c0o, [&](int c, float4 v) {
                if (c < PDIM) {
                    float b = bp[c];
                    float4 o = {v.x + b, v.y + b, v.z + b, v.w + b};
                    *(float4*)(tbuf + c * TILE + si) = o;
                }
            });
        }
        __syncthreads();

        // ---------------- rational-quadratic spline ----------------
        // parallel phase: part 0 -> widths (scr rows 0..32), part 1 -> heights
        // (rows 33..65), part 2 -> derivatives (rows 66..98). 64 samples each.
        {
            const int part = tx >> 6;     // 0..3
            const int s    = tx & 63;
            const float invscale = 0.08838834764831845f;          // 1/sqrt(128)
            const float alpha    = 1.0f - MINBIN * (float)KBINS;  // 0.968
            float* scr = hT;       // free scratch
            const float* p = tbuf; // p^T

            if (part < 2) {       // softmax -> cumsum -> knots (widths / heights)
                const int po = part * KBINS;
                const int so = part * 33;
                float m = -1e30f;
                for (int k = 0; k < KBINS; ++k)
                    m = fmaxf(m, p[(po + k) * TILE + s] * invscale);
                float S = 0.f;
                for (int k = 0; k < KBINS; ++k) {
                    float e = expf(p[(po + k) * TILE + s] * invscale - m);
                    S += e;
                    scr[(so + k + 1) * TILE + s] = e;
                }
                float inv = 1.0f / S;
                float cs = 0.f;
                scr[so * TILE + s] = -TBV;
                for (int k = 1; k < KBINS; ++k) {
                    cs += scr[(so + k) * TILE + s];
                    scr[(so + k) * TILE + s] =
                        2.0f * TBV * (MINBIN * (float)k + alpha * cs * inv) - TBV;
                }
                scr[(so + KBINS) * TILE + s] = TBV;
            } else if (part == 2) {  // derivatives
                const float dedge = MINDER + softplusf(logf(expf(1.0f - MINDER) - 1.0f));
                scr[66 * TILE + s] = dedge;
                for (int k = 1; k < KBINS; ++k)
                    scr[(66 + k) * TILE + s] =
                        MINDER + softplusf(p[(2 * KBINS + k - 1) * TILE + s]);
                scr[(66 + KBINS) * TILE + s] = dedge;
            }
        }
        __syncthreads();
        if (tx < TILE) {
            float* scr = hT;
            const float yv  = zv;
            const float ycv = fminf(fmaxf(yv, -TBV), TBV);
            const bool inside = (yv >= -TBV) && (yv <= TBV);
            int cnt = 0;
            for (int k = 0; k <= KBINS; ++k) {
                float loc = scr[k * TILE + tx];
                if (k == KBINS) loc += 1e-6f;
                cnt += (ycv >= loc) ? 1 : 0;
            }
            int idx = min(cnt - 1, KBINS - 1);
            if (idx < 0) idx = 0;
            float cwk = scr[idx * TILE + tx];
            float wk  = scr[(idx + 1) * TILE + tx] - cwk;
            float chk = scr[(33 + idx) * TILE + tx];
            float hk  = scr[(34 + idx) * TILE + tx] - chk;
            float dk  = scr[(66 + idx) * TILE + tx];
            float dk1 = scr[(67 + idx) * TILE + tx];
            float sk   = hk / wk;
            float th   = (ycv - cwk) / wk;
            float om   = 1.0f - th;
            float th1m = th * om;
            float num  = hk * (sk * th * th + dk * th1m);
            float den  = sk + (dk + dk1 - 2.0f * sk) * th1m;
            float outv = chk + num / den;
            float dnum = sk * sk * (dk1 * th * th + 2.0f * sk * th1m + dk * om * om);
            float ladl = logf(dnum) - 2.0f * logf(den);
            if (inside) { zv = outv; ladv += ladl; }
        }
        __syncthreads();
    }

    if (tx < TILE)
        outp[base + tx] = -0.5f * zv * zv - 0.91893853320467274178f + ladv;
}

extern "C" void kernel_launch(void* const* d_in, const int* in_sizes, int n_in,
                              void* d_out, int out_size)
{
    const float* y       = (const float*)d_in[0];
    const float* context = (const float*)d_in[1];
    const float* eW1     = (const float*)d_in[2];
    const float* eb1     = (const float*)d_in[3];
    const float* eW2     = (const float*)d_in[4];
    const float* eb2     = (const float*)d_in[5];
    const float* eW3     = (const float*)d_in[6];
    const float* eb3     = (const float*)d_in[7];
    const float* init_b  = (const float*)d_in[8];
    const float* ctx_W   = (const float*)d_in[9];
    const float* ctx_b   = (const float*)d_in[10];
    const float* blk_W1  = (const float*)d_in[11];
    const float* blk_b1  = (const float*)d_in[12];
    const float* blk_W2  = (const float*)d_in[13];
    const float* blk_b2  = (const float*)d_in[14];
    const float* blk_Wc  = (const float*)d_in[15];
    const float* blk_bc  = (const float*)d_in[16];
    const float* out_W   = (const float*)d_in[17];
    const float* out_b   = (const float*)d_in[18];

    const int B = in_sizes[0];          // 262144
    const int grid = B / TILE;          // 4096
    const size_t smem = (size_t)(2 * HDIM * TILE + EDIM * TILE + 4096) * sizeof(float); // 98304 B

    cudaFuncSetAttribute(nsf_kernel, cudaFuncAttributeMaxDynamicSharedMemorySize, (int)smem);
    nsf_kernel<<<grid, THREADS, smem>>>(
        y, context, eW1, eb1, eW2, eb2, eW3, eb3, init_b, ctx_W, ctx_b,
        blk_W1, blk_b1, blk_W2, blk_b2, blk_Wc, blk_bc, out_W, out_b,
        (float*)d_out);
}

// round 6
// speedup vs baseline: 1.3370x; 1.0954x over previous
#include <cuda_runtime.h>
#include <math.h>

#define THREADS 256
#define TILE    64
#define EDIM    64
#define HDIM    128
#define KBINS   32
#define PDIM    95
#define LNUM    6
#define NBNUM   2
#define TBV     6.0f
#define MINBIN  0.001f
#define MINDER  0.001f

typedef unsigned long long ull;

__device__ __forceinline__ ull dup2(float x) {
    ull r; asm("mov.b64 %0, {%1,%1};" : "=l"(r) : "f"(x)); return r;
}
__device__ __forceinline__ void unpack2(ull v, float& a, float& b) {
    asm("mov.b64 {%0,%1}, %2;" : "=f"(a), "=f"(b) : "l"(v));
}
__device__ __forceinline__ void fma2(ull& d, ull a, ull b) {
    asm("fma.rn.f32x2 %0, %1, %2, %0;" : "+l"(d) : "l"(a), "l"(b));
}

__device__ __forceinline__ void cpa16(float* s, const float* g) {
    unsigned sa = (unsigned)__cvta_generic_to_shared(s);
    asm volatile("cp.async.cg.shared.global [%0], [%1], 16;" :: "r"(sa), "l"(g));
}
__device__ __forceinline__ void cpa4(float* s, const float* g) {
    unsigned sa = (unsigned)__cvta_generic_to_shared(s);
    asm volatile("cp.async.ca.shared.global [%0], [%1], 4;" :: "r"(sa), "l"(g));
}
__device__ __forceinline__ void cp_commit() { asm volatile("cp.async.commit_group;" ::: "memory"); }
__device__ __forceinline__ void cp_wait0()  { asm volatile("cp.async.wait_group 0;" ::: "memory"); }

__device__ __forceinline__ float eluf(float x)  { return x > 0.f ? x : expm1f(x); }
__device__ __forceinline__ float sigmf(float x) { return 1.0f / (1.0f + expf(-x)); }
__device__ __forceinline__ float softplusf(float x) {
    return fmaxf(x, 0.f) + log1pf(expf(-fabsf(x)));
}

template<int NH>
__device__ __forceinline__ void zacc(ull (&a)[NH][4]) {
    #pragma unroll
    for (int i = 0; i < NH; ++i)
        #pragma unroll
        for (int j = 0; j < 4; ++j) a[i][j] = 0ull;
}

// out^T[c][i] = sum_k W[k][c] * X^T[k][i]
// cp.async double-buffered weight pipeline, 1 sync per chunk, LDS.128 w loads.
// CHUNK = KC*NSTR = 4096 floats (16KB). wbuf holds 2 slots.
// NOTE: no trailing sync — caller must sync before any epilogue that aliases Xs.
template<int NPT, int NSTR, int KC>
__device__ __forceinline__ void gemm_pipe(
    ull (&accp)[NPT/2][4],
    const float* __restrict__ Xs,
    const float* __restrict__ Wg,
    float* __restrict__ wbuf,
    int KDIM, int tx, int si, int c0)
{
    constexpr int CHUNK = KC * NSTR;                 // 4096
    constexpr int NITER = CHUNK / (4 * THREADS);     // 4
    // prologue: chunk 0 -> slot 0
    #pragma unroll
    for (int it = 0; it < NITER; ++it)
        cpa16(wbuf + (it * THREADS + tx) * 4, Wg + (it * THREADS + tx) * 4);
    cp_commit();

    const int nc = KDIM / KC;
    for (int c = 0; c < nc; ++c) {
        cp_wait0();
        __syncthreads();
        if (c + 1 < nc) {
            const float* src = Wg + (size_t)(c + 1) * CHUNK;
            float* dst = wbuf + ((c + 1) & 1) * CHUNK;
            #pragma unroll
            for (int it = 0; it < NITER; ++it)
                cpa16(dst + (it * THREADS + tx) * 4, src + (it * THREADS + tx) * 4);
            cp_commit();
        }
        const float* cur = wbuf + (c & 1) * CHUNK;
        const float* Xc  = Xs + c * KC * TILE + si;
        #pragma unroll 8
        for (int k = 0; k < KC; ++k) {
            float4 xv = *(const float4*)(Xc + k * TILE);
            ull x0 = dup2(xv.x), x1 = dup2(xv.y), x2 = dup2(xv.z), x3 = dup2(xv.w);
            const float* wr = cur + k * NSTR + c0;
            #pragma unroll
            for (int q = 0; q < NPT / 4; ++q) {
                ulonglong2 wv = *(const ulonglong2*)(wr + 4 * q);
                fma2(accp[2 * q][0], wv.x, x0);
                fma2(accp[2 * q][1], wv.x, x1);
                fma2(accp[2 * q][2], wv.x, x2);
                fma2(accp[2 * q][3], wv.x, x3);
                fma2(accp[2 * q + 1][0], wv.y, x0);
                fma2(accp[2 * q + 1][1], wv.y, x1);
                fma2(accp[2 * q + 1][2], wv.y, x2);
                fma2(accp[2 * q + 1][3], wv.y, x3);
            }
        }
    }
}

template<int NPT, class F>
__device__ __forceinline__ void epi(ull (&accp)[NPT/2][4], int c0, F f) {
    #pragma unroll
    for (int cp = 0; cp < NPT / 2; ++cp) {
        float4 vl, vh;
        unpack2(accp[cp][0], vl.x, vh.x);
        unpack2(accp[cp][1], vl.y, vh.y);
        unpack2(accp[cp][2], vl.z, vh.z);
        unpack2(accp[cp][3], vl.w, vh.w);
        f(c0 + 2 * cp,     vl);
        f(c0 + 2 * cp + 1, vh);
    }
}

__global__ void __launch_bounds__(THREADS, 2)
nsf_kernel(const float* __restrict__ y,      const float* __restrict__ context,
           const float* __restrict__ eW1,    const float* __restrict__ eb1,
           const float* __restrict__ eW2,    const float* __restrict__ eb2,
           const float* __restrict__ eW3,    const float* __restrict__ eb3,
           const float* __restrict__ init_b, const float* __restrict__ ctx_W,
           const float* __restrict__ ctx_b,  const float* __restrict__ blk_W1,
           const float* __restrict__ blk_b1, const float* __restrict__ blk_W2,
           const float* __restrict__ blk_b2, const float* __restrict__ blk_Wc,
           const float* __restrict__ blk_bc, const float* __restrict__ out_W,
           const float* __restrict__ out_b,  float* __restrict__ outp)
{
    extern __shared__ float smem[];
    float* hT   = smem;                                 // [128][64] (also spline scratch)
    float* tbuf = smem + HDIM * TILE;                   // [128][64]
    float* embT = smem + 2 * HDIM * TILE;               // [64][64]
    float* wbuf = smem + 2 * HDIM * TILE + EDIM * TILE; // 2 x 4096 floats

    const int tx   = threadIdx.x;
    const int base = blockIdx.x * TILE;
    const int si   = (tx & 15) * 4;   // sample offset within tile
    const int cg   = tx >> 4;         // column group 0..15

    // persistent spline state (threads 0..63)
    float zv = 0.f, ladv = 0.f;
    if (tx < TILE) zv = y[base + tx];

    // ---------------- embedding ----------------
    if (tx < 2 * TILE) {
        int ii = tx & 63, cd = tx >> 6;
        wbuf[cd * TILE + ii] = context[(size_t)(base + ii) * 2 + cd];
    }
    __syncthreads();
    for (int idx = tx; idx < EDIM * TILE; idx += THREADS) {
        int c = idx >> 6, ii = idx & 63;
        float v = eb1[c] + wbuf[ii] * eW1[c] + wbuf[TILE + ii] * eW1[EDIM + c];
        embT[idx] = eluf(v);
    }
    __syncthreads();     // wbuf reads done before e2 prologue overwrites it
    {
        const int c0e = cg * 4;
        ull acce[2][4];
        zacc<2>(acce);
        gemm_pipe<4, 64, 64>(acce, embT, eW2, wbuf, EDIM, tx, si, c0e);
        epi<4>(acce, c0e, [&](int c, float4 v) {
            float b = eb2[c];
            float4 o = {eluf(v.x + b), eluf(v.y + b), eluf(v.z + b), eluf(v.w + b)};
            *(float4*)(tbuf + c * TILE + si) = o;
        });
        __syncthreads();  // e2 slot-0 reads done before e3 prologue overwrites slot 0
        zacc<2>(acce);
        gemm_pipe<4, 64, 64>(acce, tbuf, eW3, wbuf, EDIM, tx, si, c0e);
        epi<4>(acce, c0e, [&](int c, float4 v) {
            float b = eb3[c];
            float4 o = {eluf(v.x + b), eluf(v.y + b), eluf(v.z + b), eluf(v.w + b)};
            *(float4*)(embT + c * TILE + si) = o;
        });
        __syncthreads();  // e3 slot-0 reads done before ctx prologue overwrites slot 0
    }

    // ---------------- flow layers ----------------
    ull acc[4][4];
    const int c0 = cg * 8;
    for (int l = 0; l < LNUM; ++l) {
        // h = init_b + emb @ ctx_W + ctx_b ; also stash elu(h) -> tbuf
        zacc<4>(acc);
        gemm_pipe<8, 128, 32>(acc, embT, ctx_W + (size_t)l * EDIM * HDIM, wbuf, EDIM, tx, si, c0);
        {
            const float* bA = init_b + l * HDIM;
            const float* bB = ctx_b  + l * HDIM;
            epi<8>(acc, c0, [&](int c, float4 v) {
                float b = bA[c] + bB[c];
                float4 o = {v.x + b, v.y + b, v.z + b, v.w + b};
                *(float4*)(hT + c * TILE + si) = o;
                float4 e = {eluf(o.x), eluf(o.y), eluf(o.z), eluf(o.w)};
                *(float4*)(tbuf + c * TILE + si) = e;
            });
        }

        for (int j = 0; j < NBNUM; ++j) {
            const int lj = l * NBNUM + j;
            // t1 = elu(elu(h) @ W1 + b1) -> tbuf
            zacc<4>(acc);
            gemm_pipe<8, 128, 32>(acc, tbuf, blk_W1 + (size_t)lj * HDIM * HDIM, wbuf, HDIM, tx, si, c0);
            __syncthreads();   // epilogue aliases X (tbuf)
            {
                const float* bp = blk_b1 + lj * HDIM;
                epi<8>(acc, c0, [&](int c, float4 v) {
                    float b = bp[c];
                    float4 o = {eluf(v.x + b), eluf(v.y + b), eluf(v.z + b), eluf(v.w + b)};
                    *(float4*)(tbuf + c * TILE + si) = o;
                });
            }
            // t2 = t1 @ W2 + b2 -> tbuf
            zacc<4>(acc);
            gemm_pipe<8, 128, 32>(acc, tbuf, blk_W2 + (size_t)lj * HDIM * HDIM, wbuf, HDIM, tx, si, c0);
            __syncthreads();   // epilogue aliases X (tbuf)
            {
                const float* bp = blk_b2 + lj * HDIM;
                epi<8>(acc, c0, [&](int c, float4 v) {
                    float b = bp[c];
                    float4 o = {v.x + b, v.y + b, v.z + b, v.w + b};
                    *(float4*)(tbuf + c * TILE + si) = o;
                });
            }
            // h += t2 * sigmoid(emb @ Wc + bc); stash elu(h) for next block
            zacc<4>(acc);
            gemm_pipe<8, 128, 32>(acc, embT, blk_Wc + (size_t)lj * EDIM * HDIM, wbuf, EDIM, tx, si, c0);
            {
                const float* bp = blk_bc + lj * HDIM;
                const bool more = (j + 1 < NBNUM);
                epi<8>(acc, c0, [&](int c, float4 v) {
                    float b = bp[c];
                    float4 t  = *(const float4*)(tbuf + c * TILE + si);
                    float4 h4 = *(const float4*)(hT   + c * TILE + si);
                    h4.x += t.x * sigmf(v.x + b);
                    h4.y += t.y * sigmf(v.y + b);
                    h4.z += t.z * sigmf(v.z + b);
                    h4.w += t.w * sigmf(v.w + b);
                    *(float4*)(hT + c * TILE + si) = h4;
                    if (more) {
                        float4 e = {eluf(h4.x), eluf(h4.y), eluf(h4.z), eluf(h4.w)};
                        *(float4*)(tbuf + c * TILE + si) = e;
                    }
                });
            }
        }

        // p^T = (h @ out_W[l] + out_b[l])^T -> tbuf  (N=95, staged stride 96)
        {
            ull acco[3][4];
            zacc<3>(acco);
            const int c0o = cg * 6;
            const float* Wg = out_W + (size_t)l * HDIM * PDIM;
            constexpr int OCH = 32 * PDIM;   // 3040 floats per chunk
            constexpr int OST = 32 * 96;     // 3072 float slot stride
            // prologue: chunk 0 -> slot 0 (stride-96 repack, 4B cp.async)
            for (int idx = tx; idx < OCH; idx += THREADS) {
                int k = idx / PDIM, c = idx - k * PDIM;
                cpa4(wbuf + k * 96 + c, Wg + idx);
            }
            cp_commit();
            for (int cch = 0; cch < 4; ++cch) {
                cp_wait0();
                __syncthreads();
                if (cch + 1 < 4) {
                    const float* src = Wg + (size_t)(cch + 1) * OCH;
                    float* dst = wbuf + ((cch + 1) & 1) * OST;
                    for (int idx = tx; idx < OCH; idx += THREADS) {
                        int k = idx / PDIM, c = idx - k * PDIM;
                        cpa4(dst + k * 96 + c, src + idx);
                    }
                    cp_commit();
                }
                const float* cur = wbuf + (cch & 1) * OST;
                #pragma unroll 8
                for (int k = 0; k < 32; ++k) {
                    float4 xv = *(const float4*)(hT + (cch * 32 + k) * TILE + si);
                    ull x0 = dup2(xv.x), x1 = dup2(xv.y), x2 = dup2(xv.z), x3 = dup2(xv.w);
                    const ull* wr = (const ull*)(cur + k * 96 + c0o);
                    #pragma unroll
                    for (int cp = 0; cp < 3; ++cp) {
                        ull w2 = wr[cp];
                        fma2(acco[cp][0], w2, x0);
                        fma2(acco[cp][1], w2, x1);
                        fma2(acco[cp][2], w2, x2);
                        fma2(acco[cp][3], w2, x3);
                    }
                }
            }
            __syncthreads();  // all hT reads done before spline scratch overwrites hT
            const float* bp = out_b + l * PDIM;
            epi<6>(acco, c0o, [&](int c, float4 v) {
                if (c < PDIM) {
                    float b = bp[c];
                    float4 o = {v.x + b, v.y + b, v.z + b, v.w + b};
                    *(float4*)(tbuf + c * TILE + si) = o;
                }
            });
        }
        __syncthreads();

        // ---------------- rational-quadratic spline ----------------
        // part 0 -> widths (scr rows 0..32), part 1 -> heights (33..65),
        // parts 2/3 -> derivatives split (66..98). 64 samples each part.
        {
            const int part = tx >> 6;     // 0..3
            const int s    = tx & 63;
            const float invscale = 0.08838834764831845f;          // 1/sqrt(128)
            const float alpha    = 1.0f - MINBIN * (float)KBINS;  // 0.968
            float* scr = hT;       // free scratch
            const float* p = tbuf; // p^T

            if (part < 2) {       // softmax -> cumsum -> knots (widths / heights)
                const int po = part * KBINS;
                const int so = part * 33;
                float m = -1e30f;
                for (int k = 0; k < KBINS; ++k)
                    m = fmaxf(m, p[(po + k) * TILE + s] * invscale);
                float S = 0.f;
                for (int k = 0; k < KBINS; ++k) {
                    float e = expf(p[(po + k) * TILE + s] * invscale - m);
                    S += e;
                    scr[(so + k + 1) * TILE + s] = e;
                }
                float inv = 1.0f / S;
                float cs = 0.f;
                scr[so * TILE + s] = -TBV;
                for (int k = 1; k < KBINS; ++k) {
                    cs += scr[(so + k) * TILE + s];
                    scr[(so + k) * TILE + s] =
                        2.0f * TBV * (MINBIN * (float)k + alpha * cs * inv) - TBV;
                }
                scr[(so + KBINS) * TILE + s] = TBV;
            } else if (part == 2) {  // derivatives k=1..16 + low edge
                const float dedge = MINDER + softplusf(logf(expf(1.0f - MINDER) - 1.0f));
                scr[66 * TILE + s] = dedge;
                for (int k = 1; k <= 16; ++k)
                    scr[(66 + k) * TILE + s] =
                        MINDER + softplusf(p[(2 * KBINS + k - 1) * TILE + s]);
            } else {                 // derivatives k=17..31 + high edge
                const float dedge = MINDER + softplusf(logf(expf(1.0f - MINDER) - 1.0f));
                for (int k = 17; k < KBINS; ++k)
                    scr[(66 + k) * TILE + s] =
                        MINDER + softplusf(p[(2 * KBINS + k - 1) * TILE + s]);
                scr[(66 + KBINS) * TILE + s] = dedge;
            }
        }
        __syncthreads();
        if (tx < TILE) {
            float* scr = hT;
            const float yv  = zv;
            const float ycv = fminf(fmaxf(yv, -TBV), TBV);
            const bool inside = (yv >= -TBV) && (yv <= TBV);
            int cnt = 0;
            for (int k = 0; k <= KBINS; ++k) {
                float loc = scr[k * TILE + tx];
                if (k == KBINS) loc += 1e-6f;
                cnt += (ycv >= loc) ? 1 : 0;
            }
            int idx = min(cnt - 1, KBINS - 1);
            if (idx < 0) idx = 0;
            float cwk = scr[idx * TILE + tx];
            float wk  = scr[(idx + 1) * TILE + tx] - cwk;
            float chk = scr[(33 + idx) * TILE + tx];
            float hk  = scr[(34 + idx) * TILE + tx] - chk;
            float dk  = scr[(66 + idx) * TILE + tx];
            float dk1 = scr[(67 + idx) * TILE + tx];
            float sk   = hk / wk;
            float th   = (ycv - cwk) / wk;
            float om   = 1.0f - th;
            float th1m = th * om;
            float num  = hk * (sk * th * th + dk * th1m);
            float den  = sk + (dk + dk1 - 2.0f * sk) * th1m;
            float outv = chk + num / den;
            float dnum = sk * sk * (dk1 * th * th + 2.0f * sk * th1m + dk * om * om);
            float ladl = logf(dnum) - 2.0f * logf(den);
            if (inside) { zv = outv; ladv += ladl; }
        }
        __syncthreads();  // spline reads of hT done before next layer overwrites it
    }

    if (tx < TILE)
        outp[base + tx] = -0.5f * zv * zv - 0.91893853320467274178f + ladv;
}

extern "C" void kernel_launch(void* const* d_in, const int* in_sizes, int n_in,
                              void* d_out, int out_size)
{
    const float* y       = (const float*)d_in[0];
    const float* context = (const float*)d_in[1];
    const float* eW1     = (const float*)d_in[2];
    const float* eb1     = (const float*)d_in[3];
    const float* eW2     = (const float*)d_in[4];
    const float* eb2     = (const float*)d_in[5];
    const float* eW3     = (const float*)d_in[6];
    const float* eb3     = (const float*)d_in[7];
    const float* init_b  = (const float*)d_in[8];
    const float* ctx_W   = (const float*)d_in[9];
    const float* ctx_b   = (const float*)d_in[10];
    const float* blk_W1  = (const float*)d_in[11];
    const float* blk_b1  = (const float*)d_in[12];
    const float* blk_W2  = (const float*)d_in[13];
    const float* blk_b2  = (const float*)d_in[14];
    const float* blk_Wc  = (const float*)d_in[15];
    const float* blk_bc  = (const float*)d_in[16];
    const float* out_W   = (const float*)d_in[17];
    const float* out_b   = (const float*)d_in[18];

    const int B = in_sizes[0];          // 262144
    const int grid = B / TILE;          // 4096
    // hT 32KB + tbuf 32KB + embT 16KB + wbuf 2x16KB = 112KB
    const size_t smem = (size_t)(2 * HDIM * TILE + EDIM * TILE + 2 * 4096) * sizeof(float);

    cudaFuncSetAttribute(nsf_kernel, cudaFuncAttributeMaxDynamicSharedMemorySize, (int)smem);
    nsf_kernel<<<grid, THREADS, smem>>>(
        y, context, eW1, eb1, eW2, eb2, eW3, eb3, init_b, ctx_W, ctx_b,
        blk_W1, blk_b1, blk_W2, blk_b2, blk_Wc, blk_bc, out_W, out_b,
        (float*)d_out);
}

// round 7
// speedup vs baseline: 1.5437x; 1.1546x over previous
#include <cuda_runtime.h>
#include <math.h>

#define THREADS 256
#define TILE    64
#define EDIM    64
#define HDIM    128
#define KBINS   32
#define PDIM    95
#define LNUM    6
#define NBNUM   2
#define TBV     6.0f
#define MINBIN  0.001f
#define MINDER  0.001f

typedef unsigned long long ull;

__device__ __forceinline__ ull dup2(float x) {
    ull r; asm("mov.b64 %0, {%1,%1};" : "=l"(r) : "f"(x)); return r;
}
__device__ __forceinline__ void unpack2(ull v, float& a, float& b) {
    asm("mov.b64 {%0,%1}, %2;" : "=f"(a), "=f"(b) : "l"(v));
}
__device__ __forceinline__ void fma2(ull& d, ull a, ull b) {
    asm("fma.rn.f32x2 %0, %1, %2, %0;" : "+l"(d) : "l"(a), "l"(b));
}

__device__ __forceinline__ void cpa16(float* s, const float* g) {
    unsigned sa = (unsigned)__cvta_generic_to_shared(s);
    asm volatile("cp.async.cg.shared.global [%0], [%1], 16;" :: "r"(sa), "l"(g));
}
__device__ __forceinline__ void cpa4(float* s, const float* g) {
    unsigned sa = (unsigned)__cvta_generic_to_shared(s);
    asm volatile("cp.async.ca.shared.global [%0], [%1], 4;" :: "r"(sa), "l"(g));
}
__device__ __forceinline__ void cp_commit() { asm volatile("cp.async.commit_group;" ::: "memory"); }
__device__ __forceinline__ void cp_wait0()  { asm volatile("cp.async.wait_group 0;" ::: "memory"); }

// fast transcendentals (MUFU-based; ample accuracy vs the 1e-3 gate)
__device__ __forceinline__ float fexp(float x)  { return __expf(x); }
__device__ __forceinline__ float flog(float x)  { return __logf(x); }
__device__ __forceinline__ float eluf(float x)  { return x > 0.f ? x : (__expf(x) - 1.0f); }
__device__ __forceinline__ float sigmf(float x) { return __fdividef(1.0f, 1.0f + __expf(-x)); }
__device__ __forceinline__ float softplusf(float x) {
    return fmaxf(x, 0.f) + __logf(1.0f + __expf(-fabsf(x)));
}

template<int NH>
__device__ __forceinline__ void zacc(ull (&a)[NH][4]) {
    #pragma unroll
    for (int i = 0; i < NH; ++i)
        #pragma unroll
        for (int j = 0; j < 4; ++j) a[i][j] = 0ull;
}

// out^T[c][i] = sum_k W[k][c] * X^T[k][i]
// cp.async double-buffered weight pipeline, 1 sync per chunk, LDS.128 w loads.
// CHUNK = KC*NSTR = 4096 floats (16KB). wbuf holds 2 slots.
// NOTE: no trailing sync — caller must sync before any epilogue that aliases Xs.
template<int NPT, int NSTR, int KC>
__device__ __forceinline__ void gemm_pipe(
    ull (&accp)[NPT/2][4],
    const float* __restrict__ Xs,
    const float* __restrict__ Wg,
    float* __restrict__ wbuf,
    int KDIM, int tx, int si, int c0)
{
    constexpr int CHUNK = KC * NSTR;                 // 4096
    constexpr int NITER = CHUNK / (4 * THREADS);     // 4
    // prologue: chunk 0 -> slot 0
    #pragma unroll
    for (int it = 0; it < NITER; ++it)
        cpa16(wbuf + (it * THREADS + tx) * 4, Wg + (it * THREADS + tx) * 4);
    cp_commit();

    const int nc = KDIM / KC;
    for (int c = 0; c < nc; ++c) {
        cp_wait0();
        __syncthreads();
        if (c + 1 < nc) {
            const float* src = Wg + (size_t)(c + 1) * CHUNK;
            float* dst = wbuf + ((c + 1) & 1) * CHUNK;
            #pragma unroll
            for (int it = 0; it < NITER; ++it)
                cpa16(dst + (it * THREADS + tx) * 4, src + (it * THREADS + tx) * 4);
            cp_commit();
        }
        const float* cur = wbuf + (c & 1) * CHUNK;
        const float* Xc  = Xs + c * KC * TILE + si;
        #pragma unroll 8
        for (int k = 0; k < KC; ++k) {
            float4 xv = *(const float4*)(Xc + k * TILE);
            ull x0 = dup2(xv.x), x1 = dup2(xv.y), x2 = dup2(xv.z), x3 = dup2(xv.w);
            const float* wr = cur + k * NSTR + c0;
            #pragma unroll
            for (int q = 0; q < NPT / 4; ++q) {
                ulonglong2 wv = *(const ulonglong2*)(wr + 4 * q);
                fma2(accp[2 * q][0], wv.x, x0);
                fma2(accp[2 * q][1], wv.x, x1);
                fma2(accp[2 * q][2], wv.x, x2);
                fma2(accp[2 * q][3], wv.x, x3);
                fma2(accp[2 * q + 1][0], wv.y, x0);
                fma2(accp[2 * q + 1][1], wv.y, x1);
                fma2(accp[2 * q + 1][2], wv.y, x2);
                fma2(accp[2 * q + 1][3], wv.y, x3);
            }
        }
    }
}

template<int NPT, class F>
__device__ __forceinline__ void epi(ull (&accp)[NPT/2][4], int c0, F f) {
    #pragma unroll
    for (int cp = 0; cp < NPT / 2; ++cp) {
        float4 vl, vh;
        unpack2(accp[cp][0], vl.x, vh.x);
        unpack2(accp[cp][1], vl.y, vh.y);
        unpack2(accp[cp][2], vl.z, vh.z);
        unpack2(accp[cp][3], vl.w, vh.w);
        f(c0 + 2 * cp,     vl);
        f(c0 + 2 * cp + 1, vh);
    }
}

__global__ void __launch_bounds__(THREADS, 2)
nsf_kernel(const float* __restrict__ y,      const float* __restrict__ context,
           const float* __restrict__ eW1,    const float* __restrict__ eb1,
           const float* __restrict__ eW2,    const float* __restrict__ eb2,
           const float* __restrict__ eW3,    const float* __restrict__ eb3,
           const float* __restrict__ init_b, const float* __restrict__ ctx_W,
           const float* __restrict__ ctx_b,  const float* __restrict__ blk_W1,
           const float* __restrict__ blk_b1, const float* __restrict__ blk_W2,
           const float* __restrict__ blk_b2, const float* __restrict__ blk_Wc,
           const float* __restrict__ blk_bc, const float* __restrict__ out_W,
           const float* __restrict__ out_b,  float* __restrict__ outp)
{
    extern __shared__ float smem[];
    float* hT   = smem;                                 // [128][64] (also spline scratch)
    float* tbuf = smem + HDIM * TILE;                   // [128][64]
    float* embT = smem + 2 * HDIM * TILE;               // [64][64]
    float* wbuf = smem + 2 * HDIM * TILE + EDIM * TILE; // 2 x 4096 floats

    const int tx   = threadIdx.x;
    const int base = blockIdx.x * TILE;
    const int si   = (tx & 15) * 4;   // sample offset within tile
    const int cg   = tx >> 4;         // column group 0..15

    // persistent spline state (threads 0..63)
    float zv = 0.f, ladv = 0.f;
    if (tx < TILE) zv = y[base + tx];

    // ---------------- embedding ----------------
    if (tx < 2 * TILE) {
        int ii = tx & 63, cd = tx >> 6;
        wbuf[cd * TILE + ii] = context[(size_t)(base + ii) * 2 + cd];
    }
    __syncthreads();
    for (int idx = tx; idx < EDIM * TILE; idx += THREADS) {
        int c = idx >> 6, ii = idx & 63;
        float v = eb1[c] + wbuf[ii] * eW1[c] + wbuf[TILE + ii] * eW1[EDIM + c];
        embT[idx] = eluf(v);
    }
    __syncthreads();     // wbuf reads done before e2 prologue overwrites it
    {
        const int c0e = cg * 4;
        ull acce[2][4];
        zacc<2>(acce);
        gemm_pipe<4, 64, 64>(acce, embT, eW2, wbuf, EDIM, tx, si, c0e);
        epi<4>(acce, c0e, [&](int c, float4 v) {
            float b = eb2[c];
            float4 o = {eluf(v.x + b), eluf(v.y + b), eluf(v.z + b), eluf(v.w + b)};
            *(float4*)(tbuf + c * TILE + si) = o;
        });
        __syncthreads();  // e2 slot-0 reads done before e3 prologue overwrites slot 0
        zacc<2>(acce);
        gemm_pipe<4, 64, 64>(acce, tbuf, eW3, wbuf, EDIM, tx, si, c0e);
        epi<4>(acce, c0e, [&](int c, float4 v) {
            float b = eb3[c];
            float4 o = {eluf(v.x + b), eluf(v.y + b), eluf(v.z + b), eluf(v.w + b)};
            *(float4*)(embT + c * TILE + si) = o;
        });
        __syncthreads();  // e3 slot-0 reads done before ctx prologue overwrites slot 0
    }

    // ---------------- flow layers ----------------
    ull acc[4][4];
    const int c0 = cg * 8;
    for (int l = 0; l < LNUM; ++l) {
        // h = init_b + emb @ ctx_W + ctx_b ; also stash elu(h) -> tbuf
        zacc<4>(acc);
        gemm_pipe<8, 128, 32>(acc, embT, ctx_W + (size_t)l * EDIM * HDIM, wbuf, EDIM, tx, si, c0);
        {
            const float* bA = init_b + l * HDIM;
            const float* bB = ctx_b  + l * HDIM;
            epi<8>(acc, c0, [&](int c, float4 v) {
                float b = bA[c] + bB[c];
                float4 o = {v.x + b, v.y + b, v.z + b, v.w + b};
                *(float4*)(hT + c * TILE + si) = o;
                float4 e = {eluf(o.x), eluf(o.y), eluf(o.z), eluf(o.w)};
                *(float4*)(tbuf + c * TILE + si) = e;
            });
        }

        for (int j = 0; j < NBNUM; ++j) {
            const int lj = l * NBNUM + j;
            // t1 = elu(elu(h) @ W1 + b1) -> tbuf
            zacc<4>(acc);
            gemm_pipe<8, 128, 32>(acc, tbuf, blk_W1 + (size_t)lj * HDIM * HDIM, wbuf, HDIM, tx, si, c0);
            __syncthreads();   // epilogue aliases X (tbuf)
            {
                const float* bp = blk_b1 + lj * HDIM;
                epi<8>(acc, c0, [&](int c, float4 v) {
                    float b = bp[c];
                    float4 o = {eluf(v.x + b), eluf(v.y + b), eluf(v.z + b), eluf(v.w + b)};
                    *(float4*)(tbuf + c * TILE + si) = o;
                });
            }
            // t2 = t1 @ W2 + b2 -> tbuf
            zacc<4>(acc);
            gemm_pipe<8, 128, 32>(acc, tbuf, blk_W2 + (size_t)lj * HDIM * HDIM, wbuf, HDIM, tx, si, c0);
            __syncthreads();   // epilogue aliases X (tbuf)
            {
                const float* bp = blk_b2 + lj * HDIM;
                epi<8>(acc, c0, [&](int c, float4 v) {
                    float b = bp[c];
                    float4 o = {v.x + b, v.y + b, v.z + b, v.w + b};
                    *(float4*)(tbuf + c * TILE + si) = o;
                });
            }
            // h += t2 * sigmoid(emb @ Wc + bc); stash elu(h) for next block
            zacc<4>(acc);
            gemm_pipe<8, 128, 32>(acc, embT, blk_Wc + (size_t)lj * EDIM * HDIM, wbuf, EDIM, tx, si, c0);
            {
                const float* bp = blk_bc + lj * HDIM;
                const bool more = (j + 1 < NBNUM);
                epi<8>(acc, c0, [&](int c, float4 v) {
                    float b = bp[c];
                    float4 t  = *(const float4*)(tbuf + c * TILE + si);
                    float4 h4 = *(const float4*)(hT   + c * TILE + si);
                    h4.x += t.x * sigmf(v.x + b);
                    h4.y += t.y * sigmf(v.y + b);
                    h4.z += t.z * sigmf(v.z + b);
                    h4.w += t.w * sigmf(v.w + b);
                    *(float4*)(hT + c * TILE + si) = h4;
                    if (more) {
                        float4 e = {eluf(h4.x), eluf(h4.y), eluf(h4.z), eluf(h4.w)};
                        *(float4*)(tbuf + c * TILE + si) = e;
                    }
                });
            }
        }

        // p^T = (h @ out_W[l] + out_b[l])^T -> tbuf  (N=95, staged stride 96)
        {
            ull acco[3][4];
            zacc<3>(acco);
            const int c0o = cg * 6;
            const float* Wg = out_W + (size_t)l * HDIM * PDIM;
            constexpr int OCH = 32 * PDIM;   // 3040 floats per chunk
            constexpr int OST = 32 * 96;     // 3072 float slot stride
            // prologue: chunk 0 -> slot 0 (stride-96 repack, 4B cp.async)
            for (int idx = tx; idx < OCH; idx += THREADS) {
                int k = idx / PDIM, c = idx - k * PDIM;
                cpa4(wbuf + k * 96 + c, Wg + idx);
            }
            cp_commit();
            for (int cch = 0; cch < 4; ++cch) {
                cp_wait0();
                __syncthreads();
                if (cch + 1 < 4) {
                    const float* src = Wg + (size_t)(cch + 1) * OCH;
                    float* dst = wbuf + ((cch + 1) & 1) * OST;
                    for (int idx = tx; idx < OCH; idx += THREADS) {
                        int k = idx / PDIM, c = idx - k * PDIM;
                        cpa4(dst + k * 96 + c, src + idx);
                    }
                    cp_commit();
                }
                const float* cur = wbuf + (cch & 1) * OST;
                #pragma unroll 8
                for (int k = 0; k < 32; ++k) {
                    float4 xv = *(const float4*)(hT + (cch * 32 + k) * TILE + si);
                    ull x0 = dup2(xv.x), x1 = dup2(xv.y), x2 = dup2(xv.z), x3 = dup2(xv.w);
                    const ull* wr = (const ull*)(cur + k * 96 + c0o);
                    #pragma unroll
                    for (int cp = 0; cp < 3; ++cp) {
                        ull w2 = wr[cp];
                        fma2(acco[cp][0], w2, x0);
                        fma2(acco[cp][1], w2, x1);
                        fma2(acco[cp][2], w2, x2);
                        fma2(acco[cp][3], w2, x3);
                    }
                }
            }
            __syncthreads();  // all hT reads done before spline scratch overwrites hT
            const float* bp = out_b + l * PDIM;
            epi<6>(acco, c0o, [&](int c, float4 v) {
                if (c < PDIM) {
                    float b = bp[c];
                    float4 o = {v.x + b, v.y + b, v.z + b, v.w + b};
                    *(float4*)(tbuf + c * TILE + si) = o;
                }
            });
        }
        __syncthreads();

        // ---------------- rational-quadratic spline ----------------
        // part 0 -> widths (scr rows 0..32), part 1 -> heights (33..65),
        // parts 2/3 -> derivatives split (66..98). 64 samples each part.
        // Softmax+cumsum held in registers; knots written to smem once.
        {
            const int part = tx >> 6;     // 0..3
            const int s    = tx & 63;
            const float invscale = 0.08838834764831845f;          // 1/sqrt(128)
            const float alpha    = 1.0f - MINBIN * (float)KBINS;  // 0.968
            float* scr = hT;       // free scratch
            const float* p = tbuf; // p^T

            if (part < 2) {       // softmax -> cumsum -> knots (widths / heights)
                const int po = part * KBINS;
                const int so = part * 33;
                float e[KBINS];
                float m = -1e30f;
                #pragma unroll
                for (int k = 0; k < KBINS; ++k) {
                    e[k] = p[(po + k) * TILE + s] * invscale;
                    m = fmaxf(m, e[k]);
                }
                float S = 0.f;
                #pragma unroll
                for (int k = 0; k < KBINS; ++k) {
                    e[k] = fexp(e[k] - m);
                    S += e[k];
                }
                float inv = __fdividef(1.0f, S);
                float cs = 0.f;
                scr[so * TILE + s] = -TBV;
                #pragma unroll
                for (int k = 1; k < KBINS; ++k) {
                    cs += e[k - 1];
                    scr[(so + k) * TILE + s] =
                        2.0f * TBV * (MINBIN * (float)k + alpha * cs * inv) - TBV;
                }
                scr[(so + KBINS) * TILE + s] = TBV;
            } else if (part == 2) {  // derivatives k=1..16 + low edge
                // edge derivative: MINDER + softplus(softplus^{-1}(1-MINDER)) == 1 exactly
                scr[66 * TILE + s] = 1.0f;
                #pragma unroll
                for (int k = 1; k <= 16; ++k)
                    scr[(66 + k) * TILE + s] =
                        MINDER + softplusf(p[(2 * KBINS + k - 1) * TILE + s]);
            } else {                 // derivatives k=17..31 + high edge
                #pragma unroll
                for (int k = 17; k < KBINS; ++k)
                    scr[(66 + k) * TILE + s] =
                        MINDER + softplusf(p[(2 * KBINS + k - 1) * TILE + s]);
                scr[(66 + KBINS) * TILE + s] = 1.0f;
            }
        }
        __syncthreads();
        if (tx < TILE) {
            float* scr = hT;
            const float yv  = zv;
            const float ycv = fminf(fmaxf(yv, -TBV), TBV);
            const bool inside = (yv >= -TBV) && (yv <= TBV);
            int cnt = 0;
            #pragma unroll
            for (int k = 0; k <= KBINS; ++k) {
                float loc = scr[k * TILE + tx];
                if (k == KBINS) loc += 1e-6f;
                cnt += (ycv >= loc) ? 1 : 0;
            }
            int idx = min(cnt - 1, KBINS - 1);
            if (idx < 0) idx = 0;
            float cwk = scr[idx * TILE + tx];
            float wk  = scr[(idx + 1) * TILE + tx] - cwk;
            float chk = scr[(33 + idx) * TILE + tx];
            float hk  = scr[(34 + idx) * TILE + tx] - chk;
            float dk  = scr[(66 + idx) * TILE + tx];
            float dk1 = scr[(67 + idx) * TILE + tx];
            float sk   = hk / wk;
            float th   = (ycv - cwk) / wk;
            float om   = 1.0f - th;
            float th1m = th * om;
            float num  = hk * (sk * th * th + dk * th1m);
            float den  = sk + (dk + dk1 - 2.0f * sk) * th1m;
            float outv = chk + num / den;
            float dnum = sk * sk * (dk1 * th * th + 2.0f * sk * th1m + dk * om * om);
            float ladl = flog(dnum) - 2.0f * flog(den);
            if (inside) { zv = outv; ladv += ladl; }
        }
        __syncthreads();  // spline reads of hT done before next layer overwrites it
    }

    if (tx < TILE)
        outp[base + tx] = -0.5f * zv * zv - 0.91893853320467274178f + ladv;
}

extern "C" void kernel_launch(void* const* d_in, const int* in_sizes, int n_in,
                              void* d_out, int out_size)
{
    const float* y       = (const float*)d_in[0];
    const float* context = (const float*)d_in[1];
    const float* eW1     = (const float*)d_in[2];
    const float* eb1     = (const float*)d_in[3];
    const float* eW2     = (const float*)d_in[4];
    const float* eb2     = (const float*)d_in[5];
    const float* eW3     = (const float*)d_in[6];
    const float* eb3     = (const float*)d_in[7];
    const float* init_b  = (const float*)d_in[8];
    const float* ctx_W   = (const float*)d_in[9];
    const float* ctx_b   = (const float*)d_in[10];
    const float* blk_W1  = (const float*)d_in[11];
    const float* blk_b1  = (const float*)d_in[12];
    const float* blk_W2  = (const float*)d_in[13];
    const float* blk_b2  = (const float*)d_in[14];
    const float* blk_Wc  = (const float*)d_in[15];
    const float* blk_bc  = (const float*)d_in[16];
    const float* out_W   = (const float*)d_in[17];
    const float* out_b   = (const float*)d_in[18];

    const int B = in_sizes[0];          // 262144
    const int grid = B / TILE;          // 4096
    // hT 32KB + tbuf 32KB + embT 16KB + wbuf 2x16KB = 112KB
    const size_t smem = (size_t)(2 * HDIM * TILE + EDIM * TILE + 2 * 4096) * sizeof(float);

    cudaFuncSetAttribute(nsf_kernel, cudaFuncAttributeMaxDynamicSharedMemorySize, (int)smem);
    nsf_kernel<<<grid, THREADS, smem>>>(
        y, context, eW1, eb1, eW2, eb2, eW3, eb3, init_b, ctx_W, ctx_b,
        blk_W1, blk_b1, blk_W2, blk_b2, blk_Wc, blk_bc, out_W, out_b,
        (float*)d_out);
}